// round 1
// baseline (speedup 1.0000x reference)
#include <cuda_runtime.h>

// SSIM loss, fused single-pass tiled kernel.
// Fields filtered: a, b, p=a^2+b^2, q=a*b  (4 instead of 5: SSIM only needs
// sigma1^2+sigma2^2 and sigma12). All Gaussian weights are compile-time
// immediates -> FFMA-imm (rt 1 on sm_103a).

#define TILE 32
#define EXT  42          // TILE + 2*5 halo
#define SINS 43          // sIn row stride (float4 units), odd -> conflict-free
#define SHS  33          // sH row stride (float4 units)
#define NT   256
#define IMG  512

// Gaussian(sigma=1.5, ksize=11), normalized (precomputed in double).
#define KW0 0.0010283801f
#define KW1 0.0075987582f
#define KW2 0.0360007696f
#define KW3 0.1093606947f
#define KW4 0.2130055430f
#define KW5 0.2660117300f

#define C1V 0.0001f
#define C2V 0.0009f

__global__ void ssim_zero_out(float* out) { out[0] = 0.0f; }

__global__ void __launch_bounds__(NT, 2)
ssim_fused_kernel(const float* __restrict__ img1,
                  const float* __restrict__ img2,
                  float* __restrict__ out)
{
    const float KW[11] = {KW0, KW1, KW2, KW3, KW4, KW5, KW4, KW3, KW2, KW1, KW0};

    extern __shared__ float4 smem[];
    float4* sIn = smem;               // [EXT][SINS] : (a, b, p, q) halo tile
    float4* sH  = smem + EXT * SINS;  // [EXT][SHS]  : horizontally filtered

    const int tid   = threadIdx.x;
    const int plane = blockIdx.z;                 // B*C = 48 planes
    const int base  = plane * (IMG * IMG);
    const int x0    = blockIdx.x * TILE - 5;
    const int y0    = blockIdx.y * TILE - 5;

    // ---------------- Stage 0: load halo tile, compute p,q ----------------
    #pragma unroll 2
    for (int idx = tid; idx < EXT * EXT; idx += NT) {
        int ey = idx / EXT;
        int ex = idx - ey * EXT;
        int gx = x0 + ex;
        int gy = y0 + ey;
        float a = 0.0f, b = 0.0f;
        if ((unsigned)gx < (unsigned)IMG && (unsigned)gy < (unsigned)IMG) {
            int off = base + gy * IMG + gx;
            a = __ldg(img1 + off);
            b = __ldg(img2 + off);
        }
        float p = a * a + b * b;
        float q = a * b;
        sIn[ey * SINS + ex] = make_float4(a, b, p, q);
    }
    __syncthreads();

    // ------------- Stage 1: horizontal 11-tap, 4 cols per task -------------
    // tasks = 42 rows * 8 chunks = 336; row = t % 42 so warp lanes hit
    // consecutive rows -> conflict-free LDS.128 phases.
    for (int t = tid; t < EXT * 8; t += NT) {
        int row = t % EXT;
        int c0  = (t / EXT) * 4;
        float4 win[14];
        #pragma unroll
        for (int j = 0; j < 14; ++j) win[j] = sIn[row * SINS + c0 + j];

        #pragma unroll
        for (int c = 0; c < 4; ++c) {
            float sa = 0.f, sb = 0.f, sp = 0.f, sq = 0.f;
            #pragma unroll
            for (int k = 0; k < 11; ++k) {
                float4 v = win[c + k];
                sa += KW[k] * v.x;
                sb += KW[k] * v.y;
                sp += KW[k] * v.z;
                sq += KW[k] * v.w;
            }
            sH[row * SHS + c0 + c] = make_float4(sa, sb, sp, sq);
        }
    }
    __syncthreads();

    // ------------- Stage 2: vertical 11-tap, SSIM, 4 rows per task ---------
    float loss = 0.0f;
    {
        int col = tid & 31;          // lane -> column : conflict-free
        int r0  = (tid >> 5) * 4;    // 8 row-groups of 4 output rows

        float4 acc[4];
        #pragma unroll
        for (int o = 0; o < 4; ++o) acc[o] = make_float4(0.f, 0.f, 0.f, 0.f);

        #pragma unroll
        for (int j = 0; j < 15; ++j) {
            float4 h = sH[(r0 + j) * SHS + col];
            #pragma unroll
            for (int o = 0; o < 4; ++o) {
                int k = j - o;
                if (k >= 0 && k <= 10) {
                    acc[o].x += KW[k] * h.x;
                    acc[o].y += KW[k] * h.y;
                    acc[o].z += KW[k] * h.z;
                    acc[o].w += KW[k] * h.w;
                }
            }
        }

        #pragma unroll
        for (int o = 0; o < 4; ++o) {
            float A = acc[o].x, B = acc[o].y, P = acc[o].z, Q = acc[o].w;
            float AA = A * A;
            float BB = B * B;
            float AB = A * B;
            float num = (2.0f * AB + C1V) * (2.0f * (Q - AB) + C2V);
            float den = (AA + BB + C1V) * ((P - AA - BB) + C2V);
            float ssim = __fdividef(num, den);
            float l = 0.5f - 0.5f * ssim;          // (1 - ssim)/2
            l = fminf(fmaxf(l, 0.0f), 0.5f);       // clip(1-ssim,0,1)/2
            loss += l;
        }
    }

    // ---------------- Block reduction + atomic accumulate ------------------
    #pragma unroll
    for (int s = 16; s > 0; s >>= 1)
        loss += __shfl_xor_sync(0xFFFFFFFFu, loss, s);

    __shared__ float warpsum[8];
    if ((tid & 31) == 0) warpsum[tid >> 5] = loss;
    __syncthreads();
    if (tid == 0) {
        float bsum = 0.f;
        #pragma unroll
        for (int w = 0; w < 8; ++w) bsum += warpsum[w];
        const float inv_total = 1.0f / (16.0f * 3.0f * 512.0f * 512.0f);
        atomicAdd(out, bsum * inv_total);
    }
}

extern "C" void kernel_launch(void* const* d_in, const int* in_sizes, int n_in,
                              void* d_out, int out_size)
{
    const float* img1 = (const float*)d_in[0];
    const float* img2 = (const float*)d_in[1];
    float* out = (float*)d_out;

    const int smem_bytes = (EXT * SINS + EXT * SHS) * (int)sizeof(float4); // 51072
    cudaFuncSetAttribute(ssim_fused_kernel,
                         cudaFuncAttributeMaxDynamicSharedMemorySize, smem_bytes);

    ssim_zero_out<<<1, 1>>>(out);

    dim3 grid(IMG / TILE, IMG / TILE, 48);   // 16 x 16 x 48 = 12288 blocks
    ssim_fused_kernel<<<grid, NT, smem_bytes>>>(img1, img2, out);
}

// round 2
// speedup vs baseline: 1.4592x; 1.4592x over previous
#include <cuda_runtime.h>

// SSIM loss — vertical-first fused kernel.
// Stage V: per-thread column, 11-tap vertical conv of (a,b,p=a^2+b^2,q=ab)
//          accumulated in registers straight from gmem (zero smem traffic).
// Stage H: one smem pass; 11-tap horizontal conv with 6-output register
//          window chunking; SSIM + block reduction + one atomicAdd.
// All Gaussian taps are compile-time immediates -> FFMA-imm (rt_SMSP=1).

#define NT      256
#define EXTX    64          // columns per block incl. 5+5 halo
#define TILE_X  54          // output columns per block
#define TILE_Y  48          // output rows per block
#define R       12          // output rows per thread (4 groups of 64 threads)
#define GROUPS  4
#define SVS     65          // sV row stride in float4 (odd -> conflict-free)
#define IMG     512

#define KW0 0.0010283801f
#define KW1 0.0075987582f
#define KW2 0.0360007696f
#define KW3 0.1093606947f
#define KW4 0.2130055430f
#define KW5 0.2660117300f

#define C1V 0.0001f
#define C2V 0.0009f

__global__ void ssim_zero_out(float* out) { out[0] = 0.0f; }

__global__ void __launch_bounds__(NT, 3)
ssim_vfirst_kernel(const float* __restrict__ img1,
                   const float* __restrict__ img2,
                   float* __restrict__ out)
{
    const float KW[11] = {KW0, KW1, KW2, KW3, KW4, KW5, KW4, KW3, KW2, KW1, KW0};

    extern __shared__ float4 sV[];    // [TILE_Y][SVS] vertical-filtered (a,b,p,q)

    const int tid  = threadIdx.x;
    const int base = blockIdx.z * (IMG * IMG);
    const int x0   = blockIdx.x * TILE_X;
    const int y0   = blockIdx.y * TILE_Y;

    // ---------------- Stage V: vertical 11-tap in registers ----------------
    {
        const int c  = tid & (EXTX - 1);      // column within strip
        const int g  = tid >> 6;              // row group 0..3
        const int gx = x0 - 5 + c;
        const bool xok = (unsigned)gx < (unsigned)IMG;
        const int iy0 = y0 + g * R - 5;

        float4 acc[R];
        #pragma unroll
        for (int o = 0; o < R; ++o) acc[o] = make_float4(0.f, 0.f, 0.f, 0.f);

        #pragma unroll
        for (int j = 0; j < R + 10; ++j) {
            int gy = iy0 + j;
            float a = 0.f, b = 0.f;
            if (xok && (unsigned)gy < (unsigned)IMG) {
                int off = base + gy * IMG + gx;
                a = __ldg(img1 + off);
                b = __ldg(img2 + off);
            }
            float p = a * a + b * b;
            float q = a * b;
            #pragma unroll
            for (int o = 0; o < R; ++o) {
                int k = j - o;
                if (k >= 0 && k <= 10) {
                    acc[o].x += KW[k] * a;
                    acc[o].y += KW[k] * b;
                    acc[o].z += KW[k] * p;
                    acc[o].w += KW[k] * q;
                }
            }
        }

        #pragma unroll
        for (int o = 0; o < R; ++o)
            sV[(g * R + o) * SVS + c] = acc[o];
    }
    __syncthreads();

    // ------------- Stage H: horizontal 11-tap + SSIM, 6 cols/task ----------
    float loss = 0.0f;
    for (int t = tid; t < 9 * TILE_Y; t += NT) {     // 9 chunks x 48 rows = 432
        int row = t % TILE_Y;
        int ch  = t / TILE_Y;
        int c0  = ch * 6;

        float4 w[16];
        #pragma unroll
        for (int j = 0; j < 16; ++j) w[j] = sV[row * SVS + c0 + j];

        int gy = y0 + row;
        int ox0 = x0 + c0;
        bool yok = gy < IMG;

        #pragma unroll
        for (int cc = 0; cc < 6; ++cc) {
            float A = 0.f, B = 0.f, P = 0.f, Q = 0.f;
            #pragma unroll
            for (int k = 0; k < 11; ++k) {
                float4 v = w[cc + k];
                A += KW[k] * v.x;
                B += KW[k] * v.y;
                P += KW[k] * v.z;
                Q += KW[k] * v.w;
            }
            float AA = A * A;
            float BB = B * B;
            float AB = A * B;
            float num = (2.0f * AB + C1V) * (2.0f * (Q - AB) + C2V);
            float den = (AA + BB + C1V) * ((P - AA - BB) + C2V);
            float ssim = __fdividef(num, den);
            float l = 0.5f - 0.5f * ssim;            // (1 - ssim)/2
            l = fminf(fmaxf(l, 0.0f), 0.5f);         // clip(1-ssim,0,1)/2
            if (yok && (ox0 + cc) < IMG) loss += l;
        }
    }

    // ---------------- Block reduction + atomic accumulate ------------------
    #pragma unroll
    for (int s = 16; s > 0; s >>= 1)
        loss += __shfl_xor_sync(0xFFFFFFFFu, loss, s);

    __shared__ float warpsum[NT / 32];
    if ((tid & 31) == 0) warpsum[tid >> 5] = loss;
    __syncthreads();
    if (tid == 0) {
        float bsum = 0.f;
        #pragma unroll
        for (int w = 0; w < NT / 32; ++w) bsum += warpsum[w];
        const float inv_total = 1.0f / (16.0f * 3.0f * 512.0f * 512.0f);
        atomicAdd(out, bsum * inv_total);
    }
}

extern "C" void kernel_launch(void* const* d_in, const int* in_sizes, int n_in,
                              void* d_out, int out_size)
{
    const float* img1 = (const float*)d_in[0];
    const float* img2 = (const float*)d_in[1];
    float* out = (float*)d_out;

    const int smem_bytes = TILE_Y * SVS * (int)sizeof(float4);  // 49920
    cudaFuncSetAttribute(ssim_vfirst_kernel,
                         cudaFuncAttributeMaxDynamicSharedMemorySize, smem_bytes);

    ssim_zero_out<<<1, 1>>>(out);

    dim3 grid((IMG + TILE_X - 1) / TILE_X,    // 10
              (IMG + TILE_Y - 1) / TILE_Y,    // 11
              48);
    ssim_vfirst_kernel<<<grid, NT, smem_bytes>>>(img1, img2, out);
}

// round 5
// speedup vs baseline: 2.0000x; 1.3706x over previous
#include <cuda_runtime.h>

// SSIM loss — vertical-first fused kernel, f32x2-packed math (sm_103a FFMA2).
// Fields packed as two f32x2 pairs: ab=(a,b), pq=(a^2+b^2, a*b).
// Stage V: per-thread column, 11-tap vertical conv in registers from gmem;
//          interior blocks take a predicate-free path.
// Stage H: j-streaming horizontal conv (1 LDS.128 -> 6 output accumulators),
//          SSIM epilogue (WITH clamp: ssim can be < 0), block reduction,
//          one atomicAdd.

#define NT      256
#define EXTX    64
#define TILE_X  54
#define TILE_Y  48
#define R       12
#define SVS     65          // row stride in 16B elements (odd -> conflict-free)
#define IMG     512

#define KWc0 0.0010283801f
#define KWc1 0.0075987582f
#define KWc2 0.0360007696f
#define KWc3 0.1093606947f
#define KWc4 0.2130055430f
#define KWc5 0.2660117300f

#define C1V 0.0001f
#define C2V 0.0009f

__global__ void ssim_zero_out(float* out) { out[0] = 0.0f; }

__device__ __forceinline__ unsigned long long pack2(float lo, float hi) {
    unsigned long long r;
    asm("mov.b64 %0, {%1,%2};" : "=l"(r) : "f"(lo), "f"(hi));
    return r;
}
__device__ __forceinline__ void unpack2(unsigned long long v, float& lo, float& hi) {
    asm("mov.b64 {%0,%1}, %2;" : "=f"(lo), "=f"(hi) : "l"(v));
}
__device__ __forceinline__ void fma2(unsigned long long& d,
                                     unsigned long long a,
                                     unsigned long long b) {
    asm("fma.rn.f32x2 %0, %1, %2, %0;" : "+l"(d) : "l"(a), "l"(b));
}

__global__ void __launch_bounds__(NT, 3)
ssim_f32x2_kernel(const float* __restrict__ img1,
                  const float* __restrict__ img2,
                  float* __restrict__ out)
{
    // 6 distinct symmetric weight pairs (weight duplicated into both halves)
    unsigned long long WP[6];
    WP[0] = pack2(KWc0, KWc0); WP[1] = pack2(KWc1, KWc1); WP[2] = pack2(KWc2, KWc2);
    WP[3] = pack2(KWc3, KWc3); WP[4] = pack2(KWc4, KWc4); WP[5] = pack2(KWc5, KWc5);
    #define KWP(k) WP[(k) <= 5 ? (k) : 10 - (k)]

    extern __shared__ ulonglong2 sV[];   // [TILE_Y][SVS] : (ab_pair, pq_pair)

    const int tid  = threadIdx.x;
    const int base = blockIdx.z * (IMG * IMG);
    const int x0   = blockIdx.x * TILE_X;
    const int y0   = blockIdx.y * TILE_Y;

    const bool interior = (x0 >= 5) && (x0 + EXTX - 5 <= IMG) &&
                          (y0 >= 5) && (y0 + TILE_Y + 5 <= IMG);

    // ---------------- Stage V: vertical 11-tap, registers ------------------
    {
        const int c   = tid & (EXTX - 1);
        const int g   = tid >> 6;            // row group 0..3
        const int gx  = x0 - 5 + c;
        const int iy0 = y0 + g * R - 5;

        unsigned long long accAB[R], accPQ[R];
        #pragma unroll
        for (int o = 0; o < R; ++o) { accAB[o] = 0ull; accPQ[o] = 0ull; }

        if (interior) {
            const float* p1 = img1 + base + iy0 * IMG + gx;
            const float* p2 = img2 + base + iy0 * IMG + gx;
            #pragma unroll
            for (int j = 0; j < R + 10; ++j) {
                float a = __ldg(p1 + j * IMG);
                float b = __ldg(p2 + j * IMG);
                float p = a * a + b * b;
                float q = a * b;
                unsigned long long ab = pack2(a, b);
                unsigned long long pq = pack2(p, q);
                #pragma unroll
                for (int o = 0; o < R; ++o) {
                    int k = j - o;
                    if (k >= 0 && k <= 10) {
                        fma2(accAB[o], KWP(k), ab);
                        fma2(accPQ[o], KWP(k), pq);
                    }
                }
            }
        } else {
            const bool xok = (unsigned)gx < (unsigned)IMG;
            #pragma unroll
            for (int j = 0; j < R + 10; ++j) {
                int gy = iy0 + j;
                float a = 0.f, b = 0.f;
                if (xok && (unsigned)gy < (unsigned)IMG) {
                    int off = base + gy * IMG + gx;
                    a = __ldg(img1 + off);
                    b = __ldg(img2 + off);
                }
                float p = a * a + b * b;
                float q = a * b;
                unsigned long long ab = pack2(a, b);
                unsigned long long pq = pack2(p, q);
                #pragma unroll
                for (int o = 0; o < R; ++o) {
                    int k = j - o;
                    if (k >= 0 && k <= 10) {
                        fma2(accAB[o], KWP(k), ab);
                        fma2(accPQ[o], KWP(k), pq);
                    }
                }
            }
        }

        #pragma unroll
        for (int o = 0; o < R; ++o)
            sV[(g * R + o) * SVS + c] = make_ulonglong2(accAB[o], accPQ[o]);
    }
    __syncthreads();

    // ------- Stage H: j-streaming horizontal 11-tap + SSIM, 6 cols/task ----
    float loss = 0.0f;
    for (int t = tid; t < 9 * TILE_Y; t += NT) {     // 9 chunks x 48 rows
        int row = t % TILE_Y;
        int c0  = (t / TILE_Y) * 6;

        unsigned long long oAB[6], oPQ[6];
        #pragma unroll
        for (int cc = 0; cc < 6; ++cc) { oAB[cc] = 0ull; oPQ[cc] = 0ull; }

        #pragma unroll
        for (int j = 0; j < 16; ++j) {
            ulonglong2 v = sV[row * SVS + c0 + j];
            #pragma unroll
            for (int cc = 0; cc < 6; ++cc) {
                int k = j - cc;
                if (k >= 0 && k <= 10) {
                    fma2(oAB[cc], KWP(k), v.x);
                    fma2(oPQ[cc], KWP(k), v.y);
                }
            }
        }

        int  gy  = y0 + row;
        int  ox0 = x0 + c0;
        bool yok = gy < IMG;

        #pragma unroll
        for (int cc = 0; cc < 6; ++cc) {
            float A, B, P, Q;
            unpack2(oAB[cc], A, B);
            unpack2(oPQ[cc], P, Q);
            float AB   = A * B;
            float AA   = A * A;
            float num1 = 2.0f * AB + C1V;
            float num2 = 2.0f * (Q - AB) + C2V;
            float den1 = fmaf(B, B, C1V) + AA;           // AA+BB+C1
            float den2 = (P - den1) + (C1V + C2V);       // P-AA-BB+C2
            float ssim = __fdividef(num1 * num2, den1 * den2);
            float l    = fmaf(ssim, -0.5f, 0.5f);        // (1-ssim)/2
            l = fminf(fmaxf(l, 0.0f), 0.5f);             // = clip(1-ssim,0,1)/2
            if (yok && (ox0 + cc) < IMG) loss += l;
        }
    }

    // ---------------- Block reduction + atomic accumulate ------------------
    #pragma unroll
    for (int s = 16; s > 0; s >>= 1)
        loss += __shfl_xor_sync(0xFFFFFFFFu, loss, s);

    __shared__ float warpsum[NT / 32];
    if ((tid & 31) == 0) warpsum[tid >> 5] = loss;
    __syncthreads();
    if (tid == 0) {
        float bsum = 0.f;
        #pragma unroll
        for (int w = 0; w < NT / 32; ++w) bsum += warpsum[w];
        const float inv_total = 1.0f / (16.0f * 3.0f * 512.0f * 512.0f);
        atomicAdd(out, bsum * inv_total);
    }
}

extern "C" void kernel_launch(void* const* d_in, const int* in_sizes, int n_in,
                              void* d_out, int out_size)
{
    const float* img1 = (const float*)d_in[0];
    const float* img2 = (const float*)d_in[1];
    float* out = (float*)d_out;

    const int smem_bytes = TILE_Y * SVS * (int)sizeof(ulonglong2);  // 49920
    cudaFuncSetAttribute(ssim_f32x2_kernel,
                         cudaFuncAttributeMaxDynamicSharedMemorySize, smem_bytes);

    ssim_zero_out<<<1, 1>>>(out);

    dim3 grid((IMG + TILE_X - 1) / TILE_X,    // 10
              (IMG + TILE_Y - 1) / TILE_Y,    // 11
              48);
    ssim_f32x2_kernel<<<grid, NT, smem_bytes>>>(img1, img2, out);
}